// round 7
// baseline (speedup 1.0000x reference)
#include <cuda_runtime.h>
#include <cuda_bf16.h>
#include <cstdint>
#include <math.h>

// Problem constants
#define BHC   16
#define NSEQ  4096
#define DDIM  64
#define MFEAT 256
#define EDIM  64
#define CHK   128
#define NCH   32

#define NORM_F   0.35355339059327373f
#define DIAG_C   0.0625f
#define RATIO_F  0.0625f
#define EPS_KF   1e-4f
#define EPS_DF   1e-6f

// Scratch (static device globals)
__device__ float    g_phi_q[BHC * NSEQ * MFEAT];   // 64 MiB (final phi_q)
__device__ float    g_phi_k[BHC * NSEQ * MFEAT];   // 64 MiB (E = exp(dd - diag))
__device__ float    g_S[BHC * NCH * MFEAT * EDIM]; // 32 MiB, per chunk [m 256][e 64]
__device__ float    g_z[BHC * NCH * MFEAT];
__device__ unsigned g_kmax[BHC];

// ---------------------------------------------------------------------------
__device__ __forceinline__ float tf32r(float x) {
    uint32_t u;
    asm("cvt.rna.tf32.f32 %0, %1;" : "=r"(u) : "f"(x));
    return __uint_as_float(u);
}
#define F2U(x) __float_as_uint(x)

__device__ __forceinline__ void mma8(float* c, uint32_t a0, uint32_t a1,
                                     uint32_t a2, uint32_t a3,
                                     uint32_t b0, uint32_t b1) {
    asm volatile("mma.sync.aligned.m16n8k8.row.col.f32.tf32.tf32.f32 "
                 "{%0,%1,%2,%3},{%4,%5,%6,%7},{%8,%9},{%0,%1,%2,%3};"
                 : "+f"(c[0]), "+f"(c[1]), "+f"(c[2]), "+f"(c[3])
                 : "r"(a0), "r"(a1), "r"(a2), "r"(a3), "r"(b0), "r"(b1));
}

__device__ __forceinline__ float decode_max(unsigned u) {
    return __uint_as_float((u & 0x80000000u) ? (u ^ 0x80000000u) : ~u);
}

// ---------------------------------------------------------------------------
__global__ void init_kmax_kernel() {
    if (threadIdx.x < BHC) g_kmax[threadIdx.x] = 0u;
}

// ---------------------------------------------------------------------------
// phi kernel: fp32. 16 rows per CTA, 256 threads.
// j-mapping per lane: jc = 4*lane + c (c=0..3) and 128 + 4*lane + c
//   -> proj reads are 2x LDS.128 per d (FFMA-bound), stores are stg.128.
// is_query: phi_q = RATIO*(exp(dd - diag - rowmax) + EPS)
// else:     g_phi_k = exp(dd - diag)   (no max needed!)  + atomicMax(dd) per bh
#define PSTRIDE 260
#define PHI_SMEM_FLOATS (64 * PSTRIDE + 16 * 64)
__global__ void phi_kernel(const float* __restrict__ data,
                           const float* __restrict__ proj,
                           int is_query) {
    extern __shared__ float sm[];
    float* proj_s = sm;                  // [64][260] transposed, pre-scaled
    float* q_s    = sm + 64 * PSTRIDE;   // [16][64]
    __shared__ float wmax_s[8];

    const int tid = threadIdx.x;
    const int row0 = blockIdx.x * 16;

    // stage proj [256][64] -> proj_s[d][j], fold NORM
    #pragma unroll 4
    for (int i = 0; i < 64; ++i) {
        int idx = tid + i * 256;
        int j = idx >> 6, d = idx & 63;
        proj_s[d * PSTRIDE + j] = proj[idx] * NORM_F;
    }
    #pragma unroll
    for (int i = 0; i < 4; ++i) {
        int idx = tid + i * 256;
        q_s[idx] = data[(size_t)row0 * DDIM + idx];
    }
    __syncthreads();

    const int w = tid >> 5, lane = tid & 31;
    const int jbase = lane * 4;
    float wmax = -3.4e38f;

    #pragma unroll
    for (int rr = 0; rr < 2; ++rr) {
        const int rl = w * 2 + rr;
        const size_t rowg = (size_t)row0 + rl;
        float acc[8];
        #pragma unroll
        for (int jj = 0; jj < 8; ++jj) acc[jj] = 0.f;
        float ss = 0.f;
        #pragma unroll 4
        for (int d = 0; d < 64; ++d) {
            float qv = q_s[rl * 64 + d];
            ss = fmaf(qv, qv, ss);
            float4 pa = *reinterpret_cast<const float4*>(proj_s + d * PSTRIDE + jbase);
            float4 pb = *reinterpret_cast<const float4*>(proj_s + d * PSTRIDE + 128 + jbase);
            acc[0] = fmaf(qv, pa.x, acc[0]);
            acc[1] = fmaf(qv, pa.y, acc[1]);
            acc[2] = fmaf(qv, pa.z, acc[2]);
            acc[3] = fmaf(qv, pa.w, acc[3]);
            acc[4] = fmaf(qv, pb.x, acc[4]);
            acc[5] = fmaf(qv, pb.y, acc[5]);
            acc[6] = fmaf(qv, pb.z, acc[6]);
            acc[7] = fmaf(qv, pb.w, acc[7]);
        }
        const float diag = DIAG_C * ss;
        float m8 = acc[0];
        #pragma unroll
        for (int jj = 1; jj < 8; ++jj) m8 = fmaxf(m8, acc[jj]);

        if (is_query) {
            #pragma unroll
            for (int o = 16; o > 0; o >>= 1)
                m8 = fmaxf(m8, __shfl_xor_sync(0xffffffffu, m8, o));
            float4 o0, o1;
            o0.x = RATIO_F * (expf(acc[0] - diag - m8) + EPS_KF);
            o0.y = RATIO_F * (expf(acc[1] - diag - m8) + EPS_KF);
            o0.z = RATIO_F * (expf(acc[2] - diag - m8) + EPS_KF);
            o0.w = RATIO_F * (expf(acc[3] - diag - m8) + EPS_KF);
            o1.x = RATIO_F * (expf(acc[4] - diag - m8) + EPS_KF);
            o1.y = RATIO_F * (expf(acc[5] - diag - m8) + EPS_KF);
            o1.z = RATIO_F * (expf(acc[6] - diag - m8) + EPS_KF);
            o1.w = RATIO_F * (expf(acc[7] - diag - m8) + EPS_KF);
            *reinterpret_cast<float4*>(g_phi_q + rowg * MFEAT + jbase) = o0;
            *reinterpret_cast<float4*>(g_phi_q + rowg * MFEAT + 128 + jbase) = o1;
        } else {
            float4 o0, o1;
            o0.x = expf(acc[0] - diag);
            o0.y = expf(acc[1] - diag);
            o0.z = expf(acc[2] - diag);
            o0.w = expf(acc[3] - diag);
            o1.x = expf(acc[4] - diag);
            o1.y = expf(acc[5] - diag);
            o1.z = expf(acc[6] - diag);
            o1.w = expf(acc[7] - diag);
            *reinterpret_cast<float4*>(g_phi_k + rowg * MFEAT + jbase) = o0;
            *reinterpret_cast<float4*>(g_phi_k + rowg * MFEAT + 128 + jbase) = o1;
            wmax = fmaxf(wmax, m8);
        }
    }

    if (!is_query) {
        #pragma unroll
        for (int o = 16; o > 0; o >>= 1)
            wmax = fmaxf(wmax, __shfl_xor_sync(0xffffffffu, wmax, o));
        if (lane == 0) wmax_s[w] = wmax;
        __syncthreads();
        if (tid == 0) {
            float bm = wmax_s[0];
            #pragma unroll
            for (int i = 1; i < 8; ++i) bm = fmaxf(bm, wmax_s[i]);
            unsigned u = __float_as_uint(bm);
            u = (u & 0x80000000u) ? ~u : (u | 0x80000000u);
            atomicMax(&g_kmax[blockIdx.x >> 8], u);
        }
    }
}

// ---------------------------------------------------------------------------
// chunk sums via mma: C[m=256, e=64(+z)] = phik^T[m, r=128] @ [v | 1][r, 72]
// phi_k applied as aK*E + bK at staging (aK = RATIO*exp(-mx), bK = RATIO*EPS).
#define CK_KS   0
#define CK_VS   (128 * 264)
#define CK_SMEMF (CK_VS + 128 * 72)
__global__ void __launch_bounds__(256, 1)
chunk_mma_kernel(const float* __restrict__ vin) {
    extern __shared__ float sf[];
    float* ksm = sf + CK_KS;
    float* vsm = sf + CK_VS;

    const int tid = threadIdx.x;
    const int wid = tid >> 5, lane = tid & 31;
    const int tq = lane >> 2, tr = lane & 3;
    const int qr = lane >> 3, qc = lane & 7;
    const int cix = blockIdx.x;
    const size_t base_row = (size_t)(cix / NCH) * NSEQ + (size_t)(cix % NCH) * CHK;

    const float mx = decode_max(g_kmax[cix >> 5]);
    const float aK = RATIO_F * expf(-mx);
    const float bK = RATIO_F * EPS_KF;

    // stage phi_k [128][256] -> affine -> tf32
    {
        const float4* src = reinterpret_cast<const float4*>(g_phi_k + base_row * MFEAT);
        #pragma unroll
        for (int j = 0; j < 4; ++j) {
            int r = wid * 4 + qr + 32 * j;
            #pragma unroll
            for (int i = 0; i < 8; ++i) {
                int c4 = qc + 8 * i;
                float4 t = src[r * 64 + c4];
                t.x = tf32r(fmaf(aK, t.x, bK)); t.y = tf32r(fmaf(aK, t.y, bK));
                t.z = tf32r(fmaf(aK, t.z, bK)); t.w = tf32r(fmaf(aK, t.w, bK));
                *reinterpret_cast<float4*>(ksm + r * 264 + 4 * c4) = t;
            }
        }
    }
    // stage v [128][64] + ones column
    {
        const float4* src = reinterpret_cast<const float4*>(vin + base_row * EDIM);
        #pragma unroll
        for (int j = 0; j < 4; ++j) {
            int r = wid * 4 + qr + 32 * j;
            #pragma unroll
            for (int i = 0; i < 2; ++i) {
                int c4 = qc + 8 * i;
                float4 t = src[r * 16 + c4];
                t.x = tf32r(t.x); t.y = tf32r(t.y); t.z = tf32r(t.z); t.w = tf32r(t.w);
                *reinterpret_cast<float4*>(vsm + r * 72 + 4 * c4) = t;
            }
        }
        if (tid < 128) {
            *reinterpret_cast<float4*>(vsm + tid * 72 + 64) = make_float4(1.f, 0.f, 0.f, 0.f);
            *reinterpret_cast<float4*>(vsm + tid * 72 + 68) = make_float4(0.f, 0.f, 0.f, 0.f);
        }
    }
    __syncthreads();

    const int m0 = wid * 32;
    float acc[2][9][4];
    #pragma unroll
    for (int mt = 0; mt < 2; ++mt)
        #pragma unroll
        for (int nt = 0; nt < 9; ++nt)
            #pragma unroll
            for (int i = 0; i < 4; ++i) acc[mt][nt][i] = 0.f;

    #pragma unroll 4
    for (int ks = 0; ks < 16; ++ks) {
        const int k0 = ks * 8;
        uint32_t b0[9], b1[9];
        #pragma unroll
        for (int nt = 0; nt < 9; ++nt) {
            b0[nt] = F2U(vsm[(k0 + tr) * 72 + nt * 8 + tq]);
            b1[nt] = F2U(vsm[(k0 + tr + 4) * 72 + nt * 8 + tq]);
        }
        #pragma unroll
        for (int mt = 0; mt < 2; ++mt) {
            const int mb = m0 + mt * 16;
            uint32_t a0 = F2U(ksm[(k0 + tr) * 264 + mb + tq]);
            uint32_t a1 = F2U(ksm[(k0 + tr) * 264 + mb + tq + 8]);
            uint32_t a2 = F2U(ksm[(k0 + tr + 4) * 264 + mb + tq]);
            uint32_t a3 = F2U(ksm[(k0 + tr + 4) * 264 + mb + tq + 8]);
            #pragma unroll
            for (int nt = 0; nt < 9; ++nt)
                mma8(acc[mt][nt], a0, a1, a2, a3, b0[nt], b1[nt]);
        }
    }

    float* Sg = g_S + (size_t)cix * MFEAT * EDIM;
    float* zg = g_z + (size_t)cix * MFEAT;
    #pragma unroll
    for (int mt = 0; mt < 2; ++mt) {
        int m = m0 + mt * 16 + tq;
        #pragma unroll
        for (int nt = 0; nt < 8; ++nt) {
            int c0 = nt * 8 + 2 * tr;
            *reinterpret_cast<float2*>(Sg + m * EDIM + c0)
                = make_float2(acc[mt][nt][0], acc[mt][nt][1]);
            *reinterpret_cast<float2*>(Sg + (m + 8) * EDIM + c0)
                = make_float2(acc[mt][nt][2], acc[mt][nt][3]);
        }
        if (tr == 0) {
            zg[m]     = acc[mt][8][0];
            zg[m + 8] = acc[mt][8][2];
        }
    }
}

// ---------------------------------------------------------------------------
__global__ void prefix_kernel() {
    const int idx = blockIdx.x * blockDim.x + threadIdx.x;
    const int T1 = BHC * MFEAT * EDIM;
    if (idx < T1) {
        int bh = idx / (MFEAT * EDIM);
        int rem = idx % (MFEAT * EDIM);
        size_t base = (size_t)bh * NCH * MFEAT * EDIM + rem;
        float run = 0.f;
        #pragma unroll
        for (int c = 0; c < NCH; ++c) {
            size_t p = base + (size_t)c * MFEAT * EDIM;
            float t = g_S[p]; g_S[p] = run; run += t;
        }
    } else if (idx < T1 + BHC * MFEAT) {
        int j = idx - T1;
        int bh = j / MFEAT;
        int rem = j % MFEAT;
        size_t base = (size_t)bh * NCH * MFEAT + rem;
        float run = 0.f;
        #pragma unroll
        for (int c = 0; c < NCH; ++c) {
            size_t p = base + (size_t)c * MFEAT;
            float t = g_z[p]; g_z[p] = run; run += t;
        }
    }
}

// ---------------------------------------------------------------------------
// out kernel (tf32 mma): per (bh, chunk)
#define SA 140
#define SB 72
#define BUFA 0
#define BUFB (128 * SA)
#define BUFS (2 * 128 * SA)
#define ZSO  (BUFS + 128 * SB)
#define QZ2O (ZSO + 256)
#define SQ2O (QZ2O + 256)
#define SUMO (SQ2O + 256)
#define DENO (SUMO + 128)
#define OUT_SMEMF (DENO + 128)

__global__ void __launch_bounds__(256, 1)
out_mma_kernel(const float* __restrict__ vin, float* __restrict__ outp) {
    extern __shared__ float sf[];
    float* bufA = sf + BUFA;
    float* bufB = sf + BUFB;
    float* bufS = sf + BUFS;
    float* zs   = sf + ZSO;
    float* qz2  = sf + QZ2O;
    float* sq2  = sf + SQ2O;
    float* sums = sf + SUMO;
    float* den  = sf + DENO;

    const int tid = threadIdx.x;
    const int wid = tid >> 5, lane = tid & 31;
    const int tq = lane >> 2, tr = lane & 3;
    const int qr = lane >> 3, qc = lane & 7;
    const int cix = blockIdx.x;
    const size_t base_row = (size_t)(cix / NCH) * NSEQ + (size_t)(cix % NCH) * CHK;
    const int m0 = wid * 16;

    const float mx = decode_max(g_kmax[cix >> 5]);
    const float aK = RATIO_F * expf(-mx);
    const float bK = RATIO_F * EPS_KF;

    zs[tid] = g_z[(size_t)cix * MFEAT + tid];

    float sacc[16][4];
    float iacc[8][4];
    #pragma unroll
    for (int nt = 0; nt < 16; ++nt)
        #pragma unroll
        for (int i = 0; i < 4; ++i) sacc[nt][i] = 0.f;
    #pragma unroll
    for (int nt = 0; nt < 8; ++nt)
        #pragma unroll
        for (int i = 0; i < 4; ++i) iacc[nt][i] = 0.f;

    float qzr = 0.f, sqr = 0.f;
    const float4* gq4 = reinterpret_cast<const float4*>(g_phi_q + base_row * MFEAT);
    const float4* gk4 = reinterpret_cast<const float4*>(g_phi_k + base_row * MFEAT);

    for (int h = 0; h < 2; ++h) {
        __syncthreads();
        const float4* Sg4 = reinterpret_cast<const float4*>(
            g_S + (size_t)cix * MFEAT * EDIM + (size_t)h * 128 * EDIM);
        #pragma unroll
        for (int j = 0; j < 4; ++j) {
            int r = wid * 4 + qr + 32 * j;
            #pragma unroll
            for (int i = 0; i < 4; ++i) {
                int c4 = qc + 8 * i;
                float4 tA = gq4[r * 64 + h * 32 + c4];
                float4 tB = gk4[r * 64 + h * 32 + c4];
                tA.x = tf32r(tA.x); tA.y = tf32r(tA.y); tA.z = tf32r(tA.z); tA.w = tf32r(tA.w);
                tB.x = tf32r(fmaf(aK, tB.x, bK)); tB.y = tf32r(fmaf(aK, tB.y, bK));
                tB.z = tf32r(fmaf(aK, tB.z, bK)); tB.w = tf32r(fmaf(aK, tB.w, bK));
                *reinterpret_cast<float4*>(bufA + r * SA + 4 * c4) = tA;
                *reinterpret_cast<float4*>(bufB + r * SA + 4 * c4) = tB;
            }
            #pragma unroll
            for (int i = 0; i < 2; ++i) {
                int c4 = qc + 8 * i;
                float4 tS = Sg4[r * 16 + c4];
                tS.x = tf32r(tS.x); tS.y = tf32r(tS.y); tS.z = tf32r(tS.z); tS.w = tf32r(tS.w);
                *reinterpret_cast<float4*>(bufS + r * SB + 4 * c4) = tS;
            }
        }
        __syncthreads();

        #pragma unroll 2
        for (int ks = 0; ks < 16; ++ks) {
            const int k0 = ks * 8;
            uint32_t a0 = F2U(bufA[(m0 + tq) * SA + k0 + tr]);
            uint32_t a1 = F2U(bufA[(m0 + tq + 8) * SA + k0 + tr]);
            uint32_t a2 = F2U(bufA[(m0 + tq) * SA + k0 + tr + 4]);
            uint32_t a3 = F2U(bufA[(m0 + tq + 8) * SA + k0 + tr + 4]);
            #pragma unroll
            for (int nt = 0; nt < 16; ++nt) {
                uint32_t b0 = F2U(bufB[(nt * 8 + tq) * SA + k0 + tr]);
                uint32_t b1 = F2U(bufB[(nt * 8 + tq) * SA + k0 + tr + 4]);
                mma8(sacc[nt], a0, a1, a2, a3, b0, b1);
            }
            #pragma unroll
            for (int nt = 0; nt < 8; ++nt) {
                uint32_t b0 = F2U(bufS[(k0 + tr) * SB + nt * 8 + tq]);
                uint32_t b1 = F2U(bufS[(k0 + tr + 4) * SB + nt * 8 + tq]);
                mma8(iacc[nt], a0, a1, a2, a3, b0, b1);
            }
        }
        {
            const float* pq = bufA + (tid >> 1) * SA + (tid & 1) * 64;
            const float* pz = zs + h * 128 + (tid & 1) * 64;
            #pragma unroll 8
            for (int j = 0; j < 64; ++j) {
                qzr = fmaf(pq[j], pz[j], qzr);
                sqr += pq[j];
            }
        }
    }

    __syncthreads();

    // epilogue: masked scores -> bufA, rowsums -> sums
    const int rlo = m0 + tq, rhi = rlo + 8;
    {
        float rsl = 0.f, rsh = 0.f;
        #pragma unroll
        for (int nt = 0; nt < 16; ++nt) {
            int c0 = nt * 8 + 2 * tr;
            float s0 = (c0     <= rlo) ? sacc[nt][0] : 0.f;
            float s1 = (c0 + 1 <= rlo) ? sacc[nt][1] : 0.f;
            float s2 = (c0     <= rhi) ? sacc[nt][2] : 0.f;
            float s3 = (c0 + 1 <= rhi) ? sacc[nt][3] : 0.f;
            rsl += s0 + s1; rsh += s2 + s3;
            *reinterpret_cast<float2*>(bufA + rlo * SA + c0) = make_float2(tf32r(s0), tf32r(s1));
            *reinterpret_cast<float2*>(bufA + rhi * SA + c0) = make_float2(tf32r(s2), tf32r(s3));
        }
        rsl += __shfl_xor_sync(0xffffffffu, rsl, 1);
        rsl += __shfl_xor_sync(0xffffffffu, rsl, 2);
        rsh += __shfl_xor_sync(0xffffffffu, rsh, 1);
        rsh += __shfl_xor_sync(0xffffffffu, rsh, 2);
        if (tr == 0) { sums[rlo] = rsl; sums[rhi] = rsh; }
    }
    // stage v -> bufB (stride SB)
    {
        const float4* vg4 = reinterpret_cast<const float4*>(vin + base_row * EDIM);
        #pragma unroll
        for (int j = 0; j < 4; ++j) {
            int r = wid * 4 + qr + 32 * j;
            #pragma unroll
            for (int i = 0; i < 2; ++i) {
                int c4 = qc + 8 * i;
                float4 t = vg4[r * 16 + c4];
                t.x = tf32r(t.x); t.y = tf32r(t.y); t.z = tf32r(t.z); t.w = tf32r(t.w);
                *reinterpret_cast<float4*>(bufB + r * SB + 4 * c4) = t;
            }
        }
    }
    qz2[tid] = qzr; sq2[tid] = sqr;
    __syncthreads();

    if (tid < 128) {
        float d = qz2[2 * tid] + qz2[2 * tid + 1] + sums[tid]
                + EPS_DF * (sq2[2 * tid] + sq2[2 * tid + 1]);
        den[tid] = 1.f / d;
    }

    // intra: iacc += masked_scores @ v
    #pragma unroll 2
    for (int ks = 0; ks < 16; ++ks) {
        const int k0 = ks * 8;
        uint32_t a0 = F2U(bufA[(m0 + tq) * SA + k0 + tr]);
        uint32_t a1 = F2U(bufA[(m0 + tq + 8) * SA + k0 + tr]);
        uint32_t a2 = F2U(bufA[(m0 + tq) * SA + k0 + tr + 4]);
        uint32_t a3 = F2U(bufA[(m0 + tq + 8) * SA + k0 + tr + 4]);
        #pragma unroll
        for (int nt = 0; nt < 8; ++nt) {
            uint32_t b0 = F2U(bufB[(k0 + tr) * SB + nt * 8 + tq]);
            uint32_t b1 = F2U(bufB[(k0 + tr + 4) * SB + nt * 8 + tq]);
            mma8(iacc[nt], a0, a1, a2, a3, b0, b1);
        }
    }
    __syncthreads();

    // final: out = iacc * inv_den
    {
        float il = den[rlo], ih = den[rhi];
        float* olo = outp + (base_row + rlo) * EDIM;
        float* ohi = outp + (base_row + rhi) * EDIM;
        #pragma unroll
        for (int nt = 0; nt < 8; ++nt) {
            int c0 = nt * 8 + 2 * tr;
            *reinterpret_cast<float2*>(olo + c0) = make_float2(iacc[nt][0] * il, iacc[nt][1] * il);
            *reinterpret_cast<float2*>(ohi + c0) = make_float2(iacc[nt][2] * ih, iacc[nt][3] * ih);
        }
    }
}

// ---------------------------------------------------------------------------
extern "C" void kernel_launch(void* const* d_in, const int* in_sizes, int n_in,
                              void* d_out, int out_size) {
    const float* big[3] = {nullptr, nullptr, nullptr};
    const float* proj = nullptr;
    int nb = 0;
    for (int i = 0; i < n_in; ++i) {
        if (in_sizes[i] == MFEAT * DDIM) proj = (const float*)d_in[i];
        else if (nb < 3) big[nb++] = (const float*)d_in[i];
    }
    const float* q = big[0];
    const float* k = big[1];
    const float* v = big[2];
    float* out = (float*)d_out;

    cudaFuncSetAttribute(phi_kernel, cudaFuncAttributeMaxDynamicSharedMemorySize,
                         PHI_SMEM_FLOATS * (int)sizeof(float));
    cudaFuncSetAttribute(chunk_mma_kernel, cudaFuncAttributeMaxDynamicSharedMemorySize,
                         CK_SMEMF * (int)sizeof(float));
    cudaFuncSetAttribute(out_mma_kernel, cudaFuncAttributeMaxDynamicSharedMemorySize,
                         OUT_SMEMF * (int)sizeof(float));

    init_kmax_kernel<<<1, 32>>>();
    phi_kernel<<<BHC * NSEQ / 16, 256, PHI_SMEM_FLOATS * sizeof(float)>>>(q, proj, 1);
    phi_kernel<<<BHC * NSEQ / 16, 256, PHI_SMEM_FLOATS * sizeof(float)>>>(k, proj, 0);
    chunk_mma_kernel<<<BHC * NCH, 256, CK_SMEMF * sizeof(float)>>>(v);
    prefix_kernel<<<(BHC * MFEAT * EDIM + BHC * MFEAT) / 256, 256>>>();
    out_mma_kernel<<<BHC * NCH, 256, OUT_SMEMF * sizeof(float)>>>(v, out);
}

// round 8
// speedup vs baseline: 1.8974x; 1.8974x over previous
#include <cuda_runtime.h>
#include <cuda_bf16.h>
#include <cstdint>
#include <math.h>

// Problem constants
#define BHC   16
#define NSEQ  4096
#define DDIM  64
#define MFEAT 256
#define EDIM  64
#define CHK   128
#define NCH   32

#define NORM_F   0.35355339059327373f
#define DIAG_C   0.0625f
#define RATIO_F  0.0625f
#define EPS_KF   1e-4f
#define EPS_DF   1e-6f

// Scratch (static device globals)
__device__ float    g_phi_q[BHC * NSEQ * MFEAT];   // 64 MiB (final phi_q)
__device__ float    g_phi_k[BHC * NSEQ * MFEAT];   // 64 MiB (E = exp(dd - diag))
__device__ float    g_S[BHC * NCH * MFEAT * EDIM]; // 32 MiB, per chunk [m 256][e 64]
__device__ float    g_z[BHC * NCH * MFEAT];
__device__ unsigned g_kmax[BHC];
__device__ float    g_proj_hi[MFEAT * DDIM];
__device__ float    g_proj_lo[MFEAT * DDIM];

// ---------------------------------------------------------------------------
__device__ __forceinline__ float tf32r(float x) {
    uint32_t u;
    asm("cvt.rna.tf32.f32 %0, %1;" : "=r"(u) : "f"(x));
    return __uint_as_float(u);
}
#define F2U(x) __float_as_uint(x)

__device__ __forceinline__ void mma8(float* c, uint32_t a0, uint32_t a1,
                                     uint32_t a2, uint32_t a3,
                                     uint32_t b0, uint32_t b1) {
    asm volatile("mma.sync.aligned.m16n8k8.row.col.f32.tf32.tf32.f32 "
                 "{%0,%1,%2,%3},{%4,%5,%6,%7},{%8,%9},{%0,%1,%2,%3};"
                 : "+f"(c[0]), "+f"(c[1]), "+f"(c[2]), "+f"(c[3])
                 : "r"(a0), "r"(a1), "r"(a2), "r"(a3), "r"(b0), "r"(b1));
}

__device__ __forceinline__ float decode_max(unsigned u) {
    return __uint_as_float((u & 0x80000000u) ? (u ^ 0x80000000u) : ~u);
}

// ---------------------------------------------------------------------------
__global__ void init_kmax_kernel() {
    if (threadIdx.x < BHC) g_kmax[threadIdx.x] = 0u;
}

// split NORM*proj into (hi, lo) tf32 pair
__global__ void proj_prep_kernel(const float* __restrict__ proj) {
    int idx = blockIdx.x * blockDim.x + threadIdx.x;
    if (idx < MFEAT * DDIM) {
        float x = proj[idx] * NORM_F;
        float hi = tf32r(x);
        g_proj_hi[idx] = hi;
        g_proj_lo[idx] = tf32r(x - hi);
    }
}

// ---------------------------------------------------------------------------
// phi via split-tf32 mma: dd[128 rows][256 j] = q[128][64] @ (NORM*proj)^T
//   dd = qhi*Phi + qhi*Plo + qlo*Phi   (fp32-accurate)
// Each warp: all 8 m-tiles x 4 n-tiles (j = wid*32 .. wid*32+31).
// Epilogue: diag from staged q; query rowmax + exp; key exp + bh atomicMax.
#define PH_QH 0
#define PH_QL (128 * 68)
#define PH_PH (2 * 128 * 68)
#define PH_PL (PH_PH + 256 * 68)
#define PH_PMAX (PH_PL + 256 * 68)            // [128][8]
#define PH_DSUM (PH_PMAX + 1024)              // [256]
#define PH_RMAX (PH_DSUM + 256)               // [128]
#define PHI_SMEMF (PH_RMAX + 128)

__global__ void __launch_bounds__(256, 1)
phi_mma_kernel(const float* __restrict__ data, int is_query) {
    extern __shared__ float sf[];
    float* qh   = sf + PH_QH;
    float* ql   = sf + PH_QL;
    float* ph   = sf + PH_PH;
    float* pl   = sf + PH_PL;
    float* pmax = sf + PH_PMAX;
    float* dsum = sf + PH_DSUM;
    float* rmax = sf + PH_RMAX;

    const int tid = threadIdx.x;
    const int wid = tid >> 5, lane = tid & 31;
    const int tq = lane >> 2, tr = lane & 3;
    const size_t base = (size_t)blockIdx.x * 128;
    float* outg = is_query ? g_phi_q : g_phi_k;

    // stage q rows [128][64] -> hi/lo (stride 68)
    {
        const float4* src = reinterpret_cast<const float4*>(data + base * DDIM);
        #pragma unroll
        for (int i = 0; i < 8; ++i) {
            int idx = tid + i * 256;
            int r = idx >> 4, c4 = idx & 15;
            float4 t = src[idx];
            float4 h, l;
            h.x = tf32r(t.x); l.x = tf32r(t.x - h.x);
            h.y = tf32r(t.y); l.y = tf32r(t.y - h.y);
            h.z = tf32r(t.z); l.z = tf32r(t.z - h.z);
            h.w = tf32r(t.w); l.w = tf32r(t.w - h.w);
            *reinterpret_cast<float4*>(qh + r * 68 + 4 * c4) = h;
            *reinterpret_cast<float4*>(ql + r * 68 + 4 * c4) = l;
        }
    }
    // stage proj hi/lo [256][64] (pre-split)
    {
        const float4* sh = reinterpret_cast<const float4*>(g_proj_hi);
        const float4* sl = reinterpret_cast<const float4*>(g_proj_lo);
        #pragma unroll
        for (int i = 0; i < 16; ++i) {
            int idx = tid + i * 256;
            int r = idx >> 4, c4 = idx & 15;
            *reinterpret_cast<float4*>(ph + r * 68 + 4 * c4) = sh[idx];
            *reinterpret_cast<float4*>(pl + r * 68 + 4 * c4) = sl[idx];
        }
    }
    __syncthreads();

    // diag partials: dsum[2r+hf] = sum over 32 k of q^2
    {
        int r = tid >> 1, hf = tid & 1;
        float s = 0.f;
        #pragma unroll 8
        for (int c = 0; c < 32; ++c) {
            float x = qh[r * 68 + hf * 32 + c] + ql[r * 68 + hf * 32 + c];
            s = fmaf(x, x, s);
        }
        dsum[tid] = s;
    }

    // mma: acc[mt][ntl][4]
    float acc[8][4][4];
    #pragma unroll
    for (int mt = 0; mt < 8; ++mt)
        #pragma unroll
        for (int nt = 0; nt < 4; ++nt)
            #pragma unroll
            for (int i = 0; i < 4; ++i) acc[mt][nt][i] = 0.f;

    const int nbase = wid * 32 + tq;
    #pragma unroll
    for (int ks = 0; ks < 8; ++ks) {
        const int k0 = ks * 8;
        uint32_t bh0[4], bh1[4], bl0[4], bl1[4];
        #pragma unroll
        for (int nt = 0; nt < 4; ++nt) {
            int n = nbase + nt * 8;
            bh0[nt] = F2U(ph[n * 68 + k0 + tr]);
            bh1[nt] = F2U(ph[n * 68 + k0 + tr + 4]);
            bl0[nt] = F2U(pl[n * 68 + k0 + tr]);
            bl1[nt] = F2U(pl[n * 68 + k0 + tr + 4]);
        }
        #pragma unroll
        for (int mt = 0; mt < 8; ++mt) {
            const int r0 = mt * 16;
            uint32_t ah0 = F2U(qh[(r0 + tq) * 68 + k0 + tr]);
            uint32_t ah1 = F2U(qh[(r0 + tq + 8) * 68 + k0 + tr]);
            uint32_t ah2 = F2U(qh[(r0 + tq) * 68 + k0 + tr + 4]);
            uint32_t ah3 = F2U(qh[(r0 + tq + 8) * 68 + k0 + tr + 4]);
            uint32_t al0 = F2U(ql[(r0 + tq) * 68 + k0 + tr]);
            uint32_t al1 = F2U(ql[(r0 + tq + 8) * 68 + k0 + tr]);
            uint32_t al2 = F2U(ql[(r0 + tq) * 68 + k0 + tr + 4]);
            uint32_t al3 = F2U(ql[(r0 + tq + 8) * 68 + k0 + tr + 4]);
            #pragma unroll
            for (int nt = 0; nt < 4; ++nt) {
                mma8(acc[mt][nt], ah0, ah1, ah2, ah3, bh0[nt], bh1[nt]);
                mma8(acc[mt][nt], ah0, ah1, ah2, ah3, bl0[nt], bl1[nt]);
                mma8(acc[mt][nt], al0, al1, al2, al3, bh0[nt], bh1[nt]);
            }
        }
    }

    // per-warp row maxima of dd (32-j slice)
    #pragma unroll
    for (int mt = 0; mt < 8; ++mt) {
        float mA = -3.4e38f, mB = -3.4e38f;
        #pragma unroll
        for (int nt = 0; nt < 4; ++nt) {
            mA = fmaxf(mA, fmaxf(acc[mt][nt][0], acc[mt][nt][1]));
            mB = fmaxf(mB, fmaxf(acc[mt][nt][2], acc[mt][nt][3]));
        }
        mA = fmaxf(mA, __shfl_xor_sync(0xffffffffu, mA, 1));
        mA = fmaxf(mA, __shfl_xor_sync(0xffffffffu, mA, 2));
        mB = fmaxf(mB, __shfl_xor_sync(0xffffffffu, mB, 1));
        mB = fmaxf(mB, __shfl_xor_sync(0xffffffffu, mB, 2));
        if (tr == 0) {
            pmax[(mt * 16 + tq) * 8 + wid] = mA;
            pmax[(mt * 16 + tq + 8) * 8 + wid] = mB;
        }
    }
    __syncthreads();

    if (tid < 128) {
        float m = pmax[tid * 8];
        #pragma unroll
        for (int w = 1; w < 8; ++w) m = fmaxf(m, pmax[tid * 8 + w]);
        rmax[tid] = m;
    }
    __syncthreads();

    if (!is_query && tid == 0) {
        float bm = rmax[0];
        #pragma unroll 8
        for (int i = 1; i < 128; ++i) bm = fmaxf(bm, rmax[i]);
        unsigned u = __float_as_uint(bm);
        u = (u & 0x80000000u) ? ~u : (u | 0x80000000u);
        atomicMax(&g_kmax[blockIdx.x >> 5], u);
    }

    // exp + store
    #pragma unroll
    for (int mt = 0; mt < 8; ++mt) {
        const int rA = mt * 16 + tq, rB = rA + 8;
        float offA = DIAG_C * (dsum[2 * rA] + dsum[2 * rA + 1]);
        float offB = DIAG_C * (dsum[2 * rB] + dsum[2 * rB + 1]);
        if (is_query) { offA += rmax[rA]; offB += rmax[rB]; }
        float* oA = outg + (base + rA) * MFEAT + wid * 32;
        float* oB = outg + (base + rB) * MFEAT + wid * 32;
        #pragma unroll
        for (int nt = 0; nt < 4; ++nt) {
            int c0 = nt * 8 + 2 * tr;
            float v0, v1, v2, v3;
            if (is_query) {
                v0 = RATIO_F * (__expf(acc[mt][nt][0] - offA) + EPS_KF);
                v1 = RATIO_F * (__expf(acc[mt][nt][1] - offA) + EPS_KF);
                v2 = RATIO_F * (__expf(acc[mt][nt][2] - offB) + EPS_KF);
                v3 = RATIO_F * (__expf(acc[mt][nt][3] - offB) + EPS_KF);
            } else {
                v0 = __expf(acc[mt][nt][0] - offA);
                v1 = __expf(acc[mt][nt][1] - offA);
                v2 = __expf(acc[mt][nt][2] - offB);
                v3 = __expf(acc[mt][nt][3] - offB);
            }
            *reinterpret_cast<float2*>(oA + c0) = make_float2(v0, v1);
            *reinterpret_cast<float2*>(oB + c0) = make_float2(v2, v3);
        }
    }
}

// ---------------------------------------------------------------------------
// chunk sums via mma: C[m=256, e=64(+z)] = phik^T[m, r=128] @ [v | 1][r, 72]
#define CK_KS   0
#define CK_VS   (128 * 264)
#define CK_SMEMF (CK_VS + 128 * 72)
__global__ void __launch_bounds__(256, 1)
chunk_mma_kernel(const float* __restrict__ vin) {
    extern __shared__ float sf[];
    float* ksm = sf + CK_KS;
    float* vsm = sf + CK_VS;

    const int tid = threadIdx.x;
    const int wid = tid >> 5, lane = tid & 31;
    const int tq = lane >> 2, tr = lane & 3;
    const int qr = lane >> 3, qc = lane & 7;
    const int cix = blockIdx.x;
    const size_t base_row = (size_t)(cix / NCH) * NSEQ + (size_t)(cix % NCH) * CHK;

    const float mx = decode_max(g_kmax[cix >> 5]);
    const float aK = RATIO_F * __expf(-mx);
    const float bK = RATIO_F * EPS_KF;

    {
        const float4* src = reinterpret_cast<const float4*>(g_phi_k + base_row * MFEAT);
        #pragma unroll
        for (int j = 0; j < 4; ++j) {
            int r = wid * 4 + qr + 32 * j;
            #pragma unroll
            for (int i = 0; i < 8; ++i) {
                int c4 = qc + 8 * i;
                float4 t = src[r * 64 + c4];
                t.x = tf32r(fmaf(aK, t.x, bK)); t.y = tf32r(fmaf(aK, t.y, bK));
                t.z = tf32r(fmaf(aK, t.z, bK)); t.w = tf32r(fmaf(aK, t.w, bK));
                *reinterpret_cast<float4*>(ksm + r * 264 + 4 * c4) = t;
            }
        }
    }
    {
        const float4* src = reinterpret_cast<const float4*>(vin + base_row * EDIM);
        #pragma unroll
        for (int j = 0; j < 4; ++j) {
            int r = wid * 4 + qr + 32 * j;
            #pragma unroll
            for (int i = 0; i < 2; ++i) {
                int c4 = qc + 8 * i;
                float4 t = src[r * 16 + c4];
                t.x = tf32r(t.x); t.y = tf32r(t.y); t.z = tf32r(t.z); t.w = tf32r(t.w);
                *reinterpret_cast<float4*>(vsm + r * 72 + 4 * c4) = t;
            }
        }
        if (tid < 128) {
            *reinterpret_cast<float4*>(vsm + tid * 72 + 64) = make_float4(1.f, 0.f, 0.f, 0.f);
            *reinterpret_cast<float4*>(vsm + tid * 72 + 68) = make_float4(0.f, 0.f, 0.f, 0.f);
        }
    }
    __syncthreads();

    const int m0 = wid * 32;
    float acc[2][9][4];
    #pragma unroll
    for (int mt = 0; mt < 2; ++mt)
        #pragma unroll
        for (int nt = 0; nt < 9; ++nt)
            #pragma unroll
            for (int i = 0; i < 4; ++i) acc[mt][nt][i] = 0.f;

    #pragma unroll 4
    for (int ks = 0; ks < 16; ++ks) {
        const int k0 = ks * 8;
        uint32_t b0[9], b1[9];
        #pragma unroll
        for (int nt = 0; nt < 9; ++nt) {
            b0[nt] = F2U(vsm[(k0 + tr) * 72 + nt * 8 + tq]);
            b1[nt] = F2U(vsm[(k0 + tr + 4) * 72 + nt * 8 + tq]);
        }
        #pragma unroll
        for (int mt = 0; mt < 2; ++mt) {
            const int mb = m0 + mt * 16;
            uint32_t a0 = F2U(ksm[(k0 + tr) * 264 + mb + tq]);
            uint32_t a1 = F2U(ksm[(k0 + tr) * 264 + mb + tq + 8]);
            uint32_t a2 = F2U(ksm[(k0 + tr + 4) * 264 + mb + tq]);
            uint32_t a3 = F2U(ksm[(k0 + tr + 4) * 264 + mb + tq + 8]);
            #pragma unroll
            for (int nt = 0; nt < 9; ++nt)
                mma8(acc[mt][nt], a0, a1, a2, a3, b0[nt], b1[nt]);
        }
    }

    float* Sg = g_S + (size_t)cix * MFEAT * EDIM;
    float* zg = g_z + (size_t)cix * MFEAT;
    #pragma unroll
    for (int mt = 0; mt < 2; ++mt) {
        int m = m0 + mt * 16 + tq;
        #pragma unroll
        for (int nt = 0; nt < 8; ++nt) {
            int c0 = nt * 8 + 2 * tr;
            *reinterpret_cast<float2*>(Sg + m * EDIM + c0)
                = make_float2(acc[mt][nt][0], acc[mt][nt][1]);
            *reinterpret_cast<float2*>(Sg + (m + 8) * EDIM + c0)
                = make_float2(acc[mt][nt][2], acc[mt][nt][3]);
        }
        if (tr == 0) {
            zg[m]     = acc[mt][8][0];
            zg[m + 8] = acc[mt][8][2];
        }
    }
}

// ---------------------------------------------------------------------------
__global__ void prefix_kernel() {
    const int idx = blockIdx.x * blockDim.x + threadIdx.x;
    const int T1 = BHC * MFEAT * EDIM;
    if (idx < T1) {
        int bh = idx / (MFEAT * EDIM);
        int rem = idx % (MFEAT * EDIM);
        size_t base = (size_t)bh * NCH * MFEAT * EDIM + rem;
        float run = 0.f;
        #pragma unroll
        for (int c = 0; c < NCH; ++c) {
            size_t p = base + (size_t)c * MFEAT * EDIM;
            float t = g_S[p]; g_S[p] = run; run += t;
        }
    } else if (idx < T1 + BHC * MFEAT) {
        int j = idx - T1;
        int bh = j / MFEAT;
        int rem = j % MFEAT;
        size_t base = (size_t)bh * NCH * MFEAT + rem;
        float run = 0.f;
        #pragma unroll
        for (int c = 0; c < NCH; ++c) {
            size_t p = base + (size_t)c * MFEAT;
            float t = g_z[p]; g_z[p] = run; run += t;
        }
    }
}

// ---------------------------------------------------------------------------
// out kernel (tf32 mma): per (bh, chunk)
#define SA 140
#define SB 72
#define BUFA 0
#define BUFB (128 * SA)
#define BUFS (2 * 128 * SA)
#define ZSO  (BUFS + 128 * SB)
#define QZ2O (ZSO + 256)
#define SQ2O (QZ2O + 256)
#define SUMO (SQ2O + 256)
#define DENO (SUMO + 128)
#define OUT_SMEMF (DENO + 128)

__global__ void __launch_bounds__(256, 1)
out_mma_kernel(const float* __restrict__ vin, float* __restrict__ outp) {
    extern __shared__ float sf[];
    float* bufA = sf + BUFA;
    float* bufB = sf + BUFB;
    float* bufS = sf + BUFS;
    float* zs   = sf + ZSO;
    float* qz2  = sf + QZ2O;
    float* sq2  = sf + SQ2O;
    float* sums = sf + SUMO;
    float* den  = sf + DENO;

    const int tid = threadIdx.x;
    const int wid = tid >> 5, lane = tid & 31;
    const int tq = lane >> 2, tr = lane & 3;
    const int qr = lane >> 3, qc = lane & 7;
    const int cix = blockIdx.x;
    const size_t base_row = (size_t)(cix / NCH) * NSEQ + (size_t)(cix % NCH) * CHK;
    const int m0 = wid * 16;

    const float mx = decode_max(g_kmax[cix >> 5]);
    const float aK = RATIO_F * __expf(-mx);
    const float bK = RATIO_F * EPS_KF;

    zs[tid] = g_z[(size_t)cix * MFEAT + tid];

    float sacc[16][4];
    float iacc[8][4];
    #pragma unroll
    for (int nt = 0; nt < 16; ++nt)
        #pragma unroll
        for (int i = 0; i < 4; ++i) sacc[nt][i] = 0.f;
    #pragma unroll
    for (int nt = 0; nt < 8; ++nt)
        #pragma unroll
        for (int i = 0; i < 4; ++i) iacc[nt][i] = 0.f;

    float qzr = 0.f, sqr = 0.f;
    const float4* gq4 = reinterpret_cast<const float4*>(g_phi_q + base_row * MFEAT);
    const float4* gk4 = reinterpret_cast<const float4*>(g_phi_k + base_row * MFEAT);

    for (int h = 0; h < 2; ++h) {
        __syncthreads();
        const float4* Sg4 = reinterpret_cast<const float4*>(
            g_S + (size_t)cix * MFEAT * EDIM + (size_t)h * 128 * EDIM);
        #pragma unroll
        for (int j = 0; j < 4; ++j) {
            int r = wid * 4 + qr + 32 * j;
            #pragma unroll
            for (int i = 0; i < 4; ++i) {
                int c4 = qc + 8 * i;
                float4 tA = gq4[r * 64 + h * 32 + c4];
                float4 tB = gk4[r * 64 + h * 32 + c4];
                tA.x = tf32r(tA.x); tA.y = tf32r(tA.y); tA.z = tf32r(tA.z); tA.w = tf32r(tA.w);
                tB.x = tf32r(fmaf(aK, tB.x, bK)); tB.y = tf32r(fmaf(aK, tB.y, bK));
                tB.z = tf32r(fmaf(aK, tB.z, bK)); tB.w = tf32r(fmaf(aK, tB.w, bK));
                *reinterpret_cast<float4*>(bufA + r * SA + 4 * c4) = tA;
                *reinterpret_cast<float4*>(bufB + r * SA + 4 * c4) = tB;
            }
            #pragma unroll
            for (int i = 0; i < 2; ++i) {
                int c4 = qc + 8 * i;
                float4 tS = Sg4[r * 16 + c4];
                tS.x = tf32r(tS.x); tS.y = tf32r(tS.y); tS.z = tf32r(tS.z); tS.w = tf32r(tS.w);
                *reinterpret_cast<float4*>(bufS + r * SB + 4 * c4) = tS;
            }
        }
        __syncthreads();

        #pragma unroll 2
        for (int ks = 0; ks < 16; ++ks) {
            const int k0 = ks * 8;
            uint32_t a0 = F2U(bufA[(m0 + tq) * SA + k0 + tr]);
            uint32_t a1 = F2U(bufA[(m0 + tq + 8) * SA + k0 + tr]);
            uint32_t a2 = F2U(bufA[(m0 + tq) * SA + k0 + tr + 4]);
            uint32_t a3 = F2U(bufA[(m0 + tq + 8) * SA + k0 + tr + 4]);
            #pragma unroll
            for (int nt = 0; nt < 16; ++nt) {
                uint32_t b0 = F2U(bufB[(nt * 8 + tq) * SA + k0 + tr]);
                uint32_t b1 = F2U(bufB[(nt * 8 + tq) * SA + k0 + tr + 4]);
                mma8(sacc[nt], a0, a1, a2, a3, b0, b1);
            }
            #pragma unroll
            for (int nt = 0; nt < 8; ++nt) {
                uint32_t b0 = F2U(bufS[(k0 + tr) * SB + nt * 8 + tq]);
                uint32_t b1 = F2U(bufS[(k0 + tr + 4) * SB + nt * 8 + tq]);
                mma8(iacc[nt], a0, a1, a2, a3, b0, b1);
            }
        }
        {
            const float* pq = bufA + (tid >> 1) * SA + (tid & 1) * 64;
            const float* pz = zs + h * 128 + (tid & 1) * 64;
            #pragma unroll 8
            for (int j = 0; j < 64; ++j) {
                qzr = fmaf(pq[j], pz[j], qzr);
                sqr += pq[j];
            }
        }
    }

    __syncthreads();

    const int rlo = m0 + tq, rhi = rlo + 8;
    {
        float rsl = 0.f, rsh = 0.f;
        #pragma unroll
        for (int nt = 0; nt < 16; ++nt) {
            int c0 = nt * 8 + 2 * tr;
            float s0 = (c0     <= rlo) ? sacc[nt][0] : 0.f;
            float s1 = (c0 + 1 <= rlo) ? sacc[nt][1] : 0.f;
            float s2 = (c0     <= rhi) ? sacc[nt][2] : 0.f;
            float s3 = (c0 + 1 <= rhi) ? sacc[nt][3] : 0.f;
            rsl += s0 + s1; rsh += s2 + s3;
            *reinterpret_cast<float2*>(bufA + rlo * SA + c0) = make_float2(tf32r(s0), tf32r(s1));
            *reinterpret_cast<float2*>(bufA + rhi * SA + c0) = make_float2(tf32r(s2), tf32r(s3));
        }
        rsl += __shfl_xor_sync(0xffffffffu, rsl, 1);
        rsl += __shfl_xor_sync(0xffffffffu, rsl, 2);
        rsh += __shfl_xor_sync(0xffffffffu, rsh, 1);
        rsh += __shfl_xor_sync(0xffffffffu, rsh, 2);
        if (tr == 0) { sums[rlo] = rsl; sums[rhi] = rsh; }
    }
    {
        const float4* vg4 = reinterpret_cast<const float4*>(vin + base_row * EDIM);
        #pragma unroll
        for (int j = 0; j < 4; ++j) {
            int r = wid * 4 + qr + 32 * j;
            #pragma unroll
            for (int i = 0; i < 2; ++i) {
                int c4 = qc + 8 * i;
                float4 t = vg4[r * 16 + c4];
                t.x = tf32r(t.x); t.y = tf32r(t.y); t.z = tf32r(t.z); t.w = tf32r(t.w);
                *reinterpret_cast<float4*>(bufB + r * SB + 4 * c4) = t;
            }
        }
    }
    qz2[tid] = qzr; sq2[tid] = sqr;
    __syncthreads();

    if (tid < 128) {
        float d = qz2[2 * tid] + qz2[2 * tid + 1] + sums[tid]
                + EPS_DF * (sq2[2 * tid] + sq2[2 * tid + 1]);
        den[tid] = 1.f / d;
    }

    #pragma unroll 2
    for (int ks = 0; ks < 16; ++ks) {
        const int k0 = ks * 8;
        uint32_t a0 = F2U(bufA[(m0 + tq) * SA + k0 + tr]);
        uint32_t a1 = F2U(bufA[(m0 + tq + 8) * SA + k0 + tr]);
        uint32_t a2 = F2U(bufA[(m0 + tq) * SA + k0 + tr + 4]);
        uint32_t a3 = F2U(bufA[(m0 + tq + 8) * SA + k0 + tr + 4]);
        #pragma unroll
        for (int nt = 0; nt < 8; ++nt) {
            uint32_t b0 = F2U(bufB[(k0 + tr) * SB + nt * 8 + tq]);
            uint32_t b1 = F2U(bufB[(k0 + tr + 4) * SB + nt * 8 + tq]);
            mma8(iacc[nt], a0, a1, a2, a3, b0, b1);
        }
    }
    __syncthreads();

    {
        float il = den[rlo], ih = den[rhi];
        float* olo = outp + (base_row + rlo) * EDIM;
        float* ohi = outp + (base_row + rhi) * EDIM;
        #pragma unroll
        for (int nt = 0; nt < 8; ++nt) {
            int c0 = nt * 8 + 2 * tr;
            *reinterpret_cast<float2*>(olo + c0) = make_float2(iacc[nt][0] * il, iacc[nt][1] * il);
            *reinterpret_cast<float2*>(ohi + c0) = make_float2(iacc[nt][2] * ih, iacc[nt][3] * ih);
        }
    }
}

// ---------------------------------------------------------------------------
extern "C" void kernel_launch(void* const* d_in, const int* in_sizes, int n_in,
                              void* d_out, int out_size) {
    const float* big[3] = {nullptr, nullptr, nullptr};
    const float* proj = nullptr;
    int nb = 0;
    for (int i = 0; i < n_in; ++i) {
        if (in_sizes[i] == MFEAT * DDIM) proj = (const float*)d_in[i];
        else if (nb < 3) big[nb++] = (const float*)d_in[i];
    }
    const float* q = big[0];
    const float* k = big[1];
    const float* v = big[2];
    float* out = (float*)d_out;

    cudaFuncSetAttribute(phi_mma_kernel, cudaFuncAttributeMaxDynamicSharedMemorySize,
                         PHI_SMEMF * (int)sizeof(float));
    cudaFuncSetAttribute(chunk_mma_kernel, cudaFuncAttributeMaxDynamicSharedMemorySize,
                         CK_SMEMF * (int)sizeof(float));
    cudaFuncSetAttribute(out_mma_kernel, cudaFuncAttributeMaxDynamicSharedMemorySize,
                         OUT_SMEMF * (int)sizeof(float));

    init_kmax_kernel<<<1, 32>>>();
    proj_prep_kernel<<<64, 256>>>(proj);
    phi_mma_kernel<<<BHC * NSEQ / 128, 256, PHI_SMEMF * sizeof(float)>>>(q, 1);
    phi_mma_kernel<<<BHC * NSEQ / 128, 256, PHI_SMEMF * sizeof(float)>>>(k, 0);
    chunk_mma_kernel<<<BHC * NCH, 256, CK_SMEMF * sizeof(float)>>>(v);
    prefix_kernel<<<(BHC * MFEAT * EDIM + BHC * MFEAT) / 256, 256>>>();
    out_mma_kernel<<<BHC * NCH, 256, OUT_SMEMF * sizeof(float)>>>(v, out);
}